// round 15
// baseline (speedup 1.0000x reference)
#include <cuda_runtime.h>
#include <math.h>
#include <stdint.h>

#define NR 400000
#define DD 128
#define GG 256

// ---------------- scratch (device globals: no allocations allowed) ----------
__device__ float d_x1[(size_t)NR * DD];   // x1 = sub@W1+b1, overwritten by se
__device__ float d_hf[(size_t)NR * DD];   // h_fused
__device__ float d_hi[(size_t)NR * DD];   // h * ginv[batch]
__device__ float d_y [(size_t)NR * DD];   // pre-BN2 score-mlp hidden
__device__ float d_logit[NR];
__device__ float d_e[NR];

__device__ float d_cs1[DD], d_cq1[DD], d_cs2[DD], d_cq2[DD];  // BN column stats
__device__ float d_a1[DD], d_c1[DD], d_a2[DD], d_c2[DD];      // BN affine params
__device__ float d_gsum[GG * DD], d_gsq[GG * DD];
__device__ float d_gmean[GG * DD], d_ginv[GG * DD];
__device__ float d_gbias[GG * DD];
__device__ float d_cnt[GG];
__device__ unsigned d_smax[GG];
__device__ float d_denom[GG];
__device__ float d_accb[GG * DD];

// ordered-uint encoding for float atomicMax
__device__ __forceinline__ unsigned f2o(float f) {
    unsigned u = __float_as_uint(f);
    return (u & 0x80000000u) ? ~u : (u | 0x80000000u);
}
__device__ __forceinline__ float o2f(unsigned u) {
    return (u & 0x80000000u) ? __uint_as_float(u & 0x7fffffffu)
                             : __uint_as_float(~u);
}

__device__ __forceinline__ void mma8(float* c, const uint32_t* a, const uint32_t* b) {
    asm volatile(
        "mma.sync.aligned.m16n8k8.row.col.f32.tf32.tf32.f32 "
        "{%0,%1,%2,%3}, {%4,%5,%6,%7}, {%8,%9}, {%0,%1,%2,%3};"
        : "+f"(c[0]), "+f"(c[1]), "+f"(c[2]), "+f"(c[3])
        : "r"(a[0]), "r"(a[1]), "r"(a[2]), "r"(a[3]), "r"(b[0]), "r"(b[1]));
}

// ---------------- init ------------------------------------------------------
__global__ void init_k() {
    int i = blockIdx.x * 128 + threadIdx.x;   // grid covers GG*DD = 32768
    d_gsum[i] = 0.f; d_gsq[i] = 0.f; d_accb[i] = 0.f;
    if (i < DD) { d_cs1[i] = 0.f; d_cq1[i] = 0.f; d_cs2[i] = 0.f; d_cq2[i] = 0.f; }
    if (i < GG) { d_cnt[i] = 0.f; d_denom[i] = 0.f; d_smax[i] = 0u; }
}

// ---------------- pure cp.async tf32 mma.sync GEMM --------------------------
// BM=128, BN=128, BK=32, 256 thr = 8 warps (4x2), warp = 32x64 (2x8 m16n8k8).
// A row-major smem (stride 36 floats), B k-major (stride 136), both cp.async,
// double-buffered, one sync per chunk.
// MODE 1: A = sub (K=64).          epi: x1 + BN1 stats + fused seg-stats(h).
// MODE 2: A = [h | se] (K=256).    epi: sigmoid gate -> h_fused, write hi.
// MODE 3: A = [hf | hi] (K=256).   epi: y = acc + bs1 - gbias[g], BN2 stats.
#define AST 36                       // A smem row stride (floats)
#define BST 136                      // B smem k-row stride (floats)
#define ASTG (128 * AST)             // 4608 floats
#define BSTG (32 * BST)              // 4352 floats
#define SMEMSZ ((2 * ASTG + 2 * BSTG) * 4 + 1024)

template<int NCHUNK, int MODE>
__global__ __launch_bounds__(256, 3) void mma_gemm(
    const float* __restrict__ A0,    // sub / h / hf
    const float* __restrict__ A1,    // -   / se / hi
    const float* __restrict__ W,     // [K,128] row-major
    const float* __restrict__ bias,
    const int*   __restrict__ batch,
    const float* __restrict__ hs)    // h (MODE 1 seg-stats)
{
    extern __shared__ __align__(16) float dyn[];
    float* sbias = dyn + 2 * ASTG + 2 * BSTG;
    int*   sbt   = (int*)(sbias + 128);

    const int t = threadIdx.x;
    const int lane = t & 31;
    const int wid  = t >> 5;
    const int warp_m = wid & 3;
    const int warp_n = wid >> 2;
    const int lr = lane >> 2, lc = lane & 3;
    const int row0 = blockIdx.x * 128;

    if (t < DD) sbias[t] = bias[t];

    float acc[2][8][4];
    #pragma unroll
    for (int i = 0; i < 2; i++)
        #pragma unroll
        for (int j = 0; j < 8; j++)
            #pragma unroll
            for (int e = 0; e < 4; e++) acc[i][j][e] = 0.f;

    auto issue = [&](int c, int s) {
        // ---- A: 128 rows x 32 floats -> row-major stride 36, 16B chunks ----
        const float* src;
        int strd;
        if (MODE == 1) { src = A0 + c * 32; strd = 64; }
        else { src = (c < 4) ? (A0 + c * 32) : (A1 + (c - 4) * 32); strd = DD; }
        uint32_t abase = (uint32_t)__cvta_generic_to_shared(dyn + s * ASTG);
        #pragma unroll
        for (int i = 0; i < 4; i++) {
            int p = t + i * 256;
            int row = p >> 3, seg = p & 7;
            uint32_t sa = abase + (uint32_t)(row * (AST * 4) + seg * 16);
            const float* ga = src + (size_t)(row0 + row) * strd + seg * 4;
            asm volatile("cp.async.cg.shared.global [%0], [%1], 16;"
                         :: "r"(sa), "l"(ga));
        }
        // ---- B: 32 k-rows x 128 floats -> k-major stride 136 ----
        uint32_t bbase = (uint32_t)__cvta_generic_to_shared(dyn + 2 * ASTG + s * BSTG);
        #pragma unroll
        for (int i = 0; i < 4; i++) {
            int p = t + i * 256;
            int krow = p >> 5, pc = p & 31;
            uint32_t sa = bbase + (uint32_t)(krow * (BST * 4) + pc * 16);
            const float* ga = W + (size_t)(c * 32 + krow) * DD + pc * 4;
            asm volatile("cp.async.cg.shared.global [%0], [%1], 16;"
                         :: "r"(sa), "l"(ga));
        }
        asm volatile("cp.async.commit_group;" ::: "memory");
    };

    issue(0, 0);
    for (int c = 0; c < NCHUNK; c++) {
        const int s = c & 1;
        asm volatile("cp.async.wait_group 0;" ::: "memory");
        __syncthreads();
        if (c + 1 < NCHUNK) issue(c + 1, 1 - s);

        const float* As = dyn + s * ASTG;
        const uint32_t* Bs = (const uint32_t*)(dyn + 2 * ASTG + s * BSTG);
        #pragma unroll
        for (int ks = 0; ks < 4; ks++) {
            const int k0 = ks * 8;
            uint32_t af[2][4];
            #pragma unroll
            for (int i = 0; i < 2; i++) {
                const float* ar = As + (warp_m * 32 + i * 16 + lr) * AST + k0 + lc;
                af[i][0] = __float_as_uint(ar[0]);
                af[i][1] = __float_as_uint(ar[8 * AST]);
                af[i][2] = __float_as_uint(ar[4]);
                af[i][3] = __float_as_uint(ar[8 * AST + 4]);
            }
            const uint32_t* b0 = &Bs[(k0 + lc) * BST + warp_n * 64 + lr];
            const uint32_t* b4 = b0 + 4 * BST;
            #pragma unroll
            for (int j = 0; j < 8; j++) {
                uint32_t bf[2] = { b0[j * 8], b4[j * 8] };
                mma8(acc[0][j], af[0], bf);
                mma8(acc[1][j], af[1], bf);
            }
        }
        __syncthreads();
    }

    // ---- epilogue ----
    // thread rows: row0 + warp_m*32 + i*16 + lr + hh*8 ; cols: warp_n*64 + j*8 + lc*2
    if (MODE == 1 || MODE == 3) {
        float* outp = (MODE == 1) ? d_x1 : d_y;
        float* gcs = (MODE == 1) ? d_cs1 : d_cs2;
        float* gcq = (MODE == 1) ? d_cq1 : d_cq2;
        float cs[8][2], cq[8][2];
        #pragma unroll
        for (int j = 0; j < 8; j++)
            #pragma unroll
            for (int e = 0; e < 2; e++) { cs[j][e] = 0.f; cq[j][e] = 0.f; }
        #pragma unroll
        for (int i = 0; i < 2; i++) {
            #pragma unroll
            for (int hh = 0; hh < 2; hh++) {
                int row = row0 + warp_m * 32 + i * 16 + lr + hh * 8;
                float* op = outp + (size_t)row * DD;
                int g = 0;
                if (MODE == 3) g = batch[row];
                #pragma unroll
                for (int j = 0; j < 8; j++) {
                    int col = warp_n * 64 + j * 8 + lc * 2;
                    float b0v = sbias[col], b1v = sbias[col + 1];
                    if (MODE == 3) {
                        float2 gb = *(const float2*)&d_gbias[g * DD + col];
                        b0v -= gb.x; b1v -= gb.y;
                    }
                    float v0 = acc[i][j][hh * 2 + 0] + b0v;
                    float v1 = acc[i][j][hh * 2 + 1] + b1v;
                    *(float2*)(op + col) = make_float2(v0, v1);
                    cs[j][0] += v0; cq[j][0] += v0 * v0;
                    cs[j][1] += v1; cq[j][1] += v1 * v1;
                }
            }
        }
        #pragma unroll
        for (int o = 4; o < 32; o <<= 1) {
            #pragma unroll
            for (int j = 0; j < 8; j++)
                #pragma unroll
                for (int e = 0; e < 2; e++) {
                    cs[j][e] += __shfl_xor_sync(0xffffffffu, cs[j][e], o);
                    cq[j][e] += __shfl_xor_sync(0xffffffffu, cq[j][e], o);
                }
        }
        if (lr == 0) {
            #pragma unroll
            for (int j = 0; j < 8; j++) {
                int col = warp_n * 64 + j * 8 + lc * 2;
                atomicAdd(&gcs[col],     cs[j][0]);
                atomicAdd(&gcs[col + 1], cs[j][1]);
                atomicAdd(&gcq[col],     cq[j][0]);
                atomicAdd(&gcq[col + 1], cq[j][1]);
            }
        }
    } else {  // MODE 2: gate sigmoid -> h_fused, and hi = h * ginv[batch]
        #pragma unroll
        for (int i = 0; i < 2; i++) {
            #pragma unroll
            for (int hh = 0; hh < 2; hh++) {
                int row = row0 + warp_m * 32 + i * 16 + lr + hh * 8;
                int g = batch[row];
                const float* hp = A0   + (size_t)row * DD;
                const float* xp = A1   + (size_t)row * DD;   // se
                float* op  = d_hf + (size_t)row * DD;
                float* oip = d_hi + (size_t)row * DD;
                #pragma unroll
                for (int j = 0; j < 8; j++) {
                    int col = warp_n * 64 + j * 8 + lc * 2;
                    float2 h2 = *(const float2*)(hp + col);
                    float2 s2 = *(const float2*)(xp + col);
                    float2 gv = *(const float2*)&d_ginv[g * DD + col];
                    float a0v = acc[i][j][hh * 2 + 0] + sbias[col];
                    float a1v = acc[i][j][hh * 2 + 1] + sbias[col + 1];
                    float g0 = 1.f / (1.f + expf(-a0v));
                    float g1 = 1.f / (1.f + expf(-a1v));
                    *(float2*)(op + col) =
                        make_float2(h2.x + g0 * s2.x, h2.y + g1 * s2.y);
                    *(float2*)(oip + col) =
                        make_float2(h2.x * gv.x, h2.y * gv.y);
                }
            }
        }
    }

    // ---- fused per-graph sum/sumsq of h (MODE 1 only, sorted segments) ----
    if (MODE == 1) {
        if (t < 128) sbt[t] = batch[row0 + t];
        __syncthreads();
        const int d = t & 127, half = t >> 7;
        const int base = half * 64;
        float s = 0.f, q = 0.f, cn = 0.f;
        int cur = sbt[base];
        for (int i = 0; i < 64; i++) {
            int g = sbt[base + i];
            if (g != cur) {
                atomicAdd(&d_gsum[cur * DD + d], s);
                atomicAdd(&d_gsq [cur * DD + d], q);
                if (d == 0) atomicAdd(&d_cnt[cur], cn);
                s = 0.f; q = 0.f; cn = 0.f; cur = g;
            }
            float v = hs[(size_t)(row0 + base + i) * DD + d];
            s += v; q += v * v; cn += 1.f;
        }
        atomicAdd(&d_gsum[cur * DD + d], s);
        atomicAdd(&d_gsq [cur * DD + d], q);
        if (d == 0) atomicAdd(&d_cnt[cur], cn);
    }
}

// ---------------- finalize BN1 + graph mean/inv-std -------------------------
__global__ void finalize1(const float* __restrict__ g1, const float* __restrict__ be1)
{
    int g = blockIdx.x, d = threadIdx.x;
    float cnt = fmaxf(d_cnt[g], 1.f);
    float m  = d_gsum[g * DD + d] / cnt;
    float sq = d_gsq [g * DD + d] / cnt;
    float sd = sqrtf(fmaxf(sq - m * m, 1e-8f));
    d_gmean[g * DD + d] = m;
    d_ginv [g * DD + d] = 1.f / (sd + 1e-8f);
    if (g == 0) {
        float mean = d_cs1[d] / (float)NR;
        float var  = d_cq1[d] / (float)NR - mean * mean;
        float a = g1[d] * rsqrtf(var + 1e-5f);
        d_a1[d] = a;
        d_c1[d] = be1[d] - mean * a;
    }
}

// ---------------- se: x1 -> relu(BN1(x1)) in place ---------------------------
__global__ void se_k() {
    int q = blockIdx.x * 256 + threadIdx.x;   // float4 idx, grid exact 50000
    float4 x = ((float4*)d_x1)[q];
    int col = (q & 31) * 4;
    float4 a = *(float4*)&d_a1[col];
    float4 c = *(float4*)&d_c1[col];
    x.x = fmaxf(a.x * x.x + c.x, 0.f);
    x.y = fmaxf(a.y * x.y + c.y, 0.f);
    x.z = fmaxf(a.z * x.z + c.z, 0.f);
    x.w = fmaxf(a.w * x.w + c.w, 0.f);
    ((float4*)d_x1)[q] = x;
}

// ---------------- gbias[g,n] = sum_k gmean*ginv*Ws1[128+k, n] ----------------
__global__ void gbias_k(const float* __restrict__ Ws1) {
    __shared__ float sm[DD];
    int g = blockIdx.x, n = threadIdx.x;
    sm[n] = d_gmean[g * DD + n] * d_ginv[g * DD + n];
    __syncthreads();
    float a = 0.f;
    #pragma unroll 4
    for (int k = 0; k < DD; k++)
        a = fmaf(sm[k], Ws1[(size_t)(DD + k) * DD + n], a);
    d_gbias[g * DD + n] = a;
}

__global__ void finalize2(const float* __restrict__ g2, const float* __restrict__ be2)
{
    int d = threadIdx.x;
    float mean = d_cs2[d] / (float)NR;
    float var  = d_cq2[d] / (float)NR - mean * mean;
    float a = g2[d] * rsqrtf(var + 1e-5f);
    d_a2[d] = a;
    d_c2[d] = be2[d] - mean * a;
}

// ---------------- score logit: warp per row ---------------------------------
__global__ void logit_k(const float* __restrict__ Ws2, const float* __restrict__ bs2,
                        const int* __restrict__ batch)
{
    int w = threadIdx.x >> 5, l = threadIdx.x & 31;
    int row = blockIdx.x * 8 + w;
    float p = 0.f;
    #pragma unroll
    for (int c = 0; c < 4; c++) {
        int col = c * 32 + l;
        float z = fmaxf(d_a2[col] * d_y[(size_t)row * DD + col] + d_c2[col], 0.f);
        p = fmaf(z, Ws2[col], p);
    }
    #pragma unroll
    for (int o = 16; o; o >>= 1) p += __shfl_down_sync(0xffffffffu, p, o);
    if (l == 0) {
        float lg = p + bs2[0];
        d_logit[row] = lg;
        atomicMax(&d_smax[batch[row]], f2o(lg));
    }
}

// ---------------- exp + segment denom ---------------------------------------
__global__ void exp_k(const int* __restrict__ batch)
{
    int r = blockIdx.x * 256 + threadIdx.x;
    if (r >= NR) return;
    int g = batch[r];
    float mx = o2f(d_smax[g]);
    float e = expf(d_logit[r] - mx);
    d_e[r] = e;
    atomicAdd(&d_denom[g], e);
}

// ---------------- weighted segment sum of h_fused * score -------------------
__global__ void wsum_k(const int* __restrict__ batch)
{
    __shared__ int   sb[256];
    __shared__ float ss[256];
    int d = threadIdx.x;
    int r0 = blockIdx.x * 256;
    for (int i = d; i < 256; i += 128) {
        int r = r0 + i;
        if (r < NR) {
            int g = batch[r];
            sb[i] = g;
            ss[i] = d_e[r] / d_denom[g];
        } else sb[i] = -1;
    }
    __syncthreads();
    float a = 0.f;
    int cur = sb[0];
    for (int i = 0; i < 256; i++) {
        int g = sb[i];
        if (g < 0) break;
        if (g != cur) {
            atomicAdd(&d_accb[cur * DD + d], a);
            a = 0.f; cur = g;
        }
        a = fmaf(d_hf[(size_t)(r0 + i) * DD + d], ss[i], a);
    }
    atomicAdd(&d_accb[cur * DD + d], a);
}

// ---------------- final mix --------------------------------------------------
__global__ void final_k(const float* __restrict__ mix, float* __restrict__ out)
{
    int g = blockIdx.x, d = threadIdx.x;
    float alpha = 1.f / (1.f + expf(-mix[0]));
    out[g * DD + d] = alpha * d_accb[g * DD + d] + (1.f - alpha) * d_gmean[g * DD + d];
}

// ---------------- launch ------------------------------------------------------
extern "C" void kernel_launch(void* const* d_in, const int* in_sizes, int n_in,
                              void* d_out, int out_size)
{
    const float* h     = (const float*)d_in[0];
    const float* sub   = (const float*)d_in[1];
    const int*   batch = (const int*)  d_in[2];
    const float* W1    = (const float*)d_in[3];
    const float* b1    = (const float*)d_in[4];
    const float* g1    = (const float*)d_in[5];
    const float* be1   = (const float*)d_in[6];
    const float* Wg    = (const float*)d_in[7];
    const float* bg    = (const float*)d_in[8];
    const float* Ws1   = (const float*)d_in[9];
    const float* bs1   = (const float*)d_in[10];
    const float* g2    = (const float*)d_in[11];
    const float* be2   = (const float*)d_in[12];
    const float* Ws2   = (const float*)d_in[13];
    const float* bs2   = (const float*)d_in[14];
    const float* mix   = (const float*)d_in[15];
    float* out = (float*)d_out;

    float* x1p; cudaGetSymbolAddress((void**)&x1p, d_x1);
    float* hfp; cudaGetSymbolAddress((void**)&hfp, d_hf);
    float* hip; cudaGetSymbolAddress((void**)&hip, d_hi);

    static int attr_done = 0;
    if (!attr_done) {
        cudaFuncSetAttribute(mma_gemm<2, 1>,
            cudaFuncAttributeMaxDynamicSharedMemorySize, SMEMSZ);
        cudaFuncSetAttribute(mma_gemm<8, 2>,
            cudaFuncAttributeMaxDynamicSharedMemorySize, SMEMSZ);
        cudaFuncSetAttribute(mma_gemm<8, 3>,
            cudaFuncAttributeMaxDynamicSharedMemorySize, SMEMSZ);
        attr_done = 1;
    }

    init_k<<<GG * DD / 128, 128>>>();
    mma_gemm<2, 1><<<NR / 128, 256, SMEMSZ>>>(sub, sub, W1, b1, batch, h);
    finalize1<<<GG, 128>>>(g1, be1);
    se_k<<<NR * DD / 4 / 256, 256>>>();                 // x1 -> se (in place)
    gbias_k<<<GG, DD>>>(Ws1);
    mma_gemm<8, 2><<<NR / 128, 256, SMEMSZ>>>(h, x1p, Wg, bg, batch, h);
    mma_gemm<8, 3><<<NR / 128, 256, SMEMSZ>>>(hfp, hip, Ws1, bs1, batch, h);
    finalize2<<<1, 128>>>(g2, be2);
    logit_k<<<NR / 8, 256>>>(Ws2, bs2, batch);
    exp_k<<<(NR + 255) / 256, 256>>>(batch);
    wsum_k<<<(NR + 255) / 256, 128>>>(batch);
    final_k<<<GG, 128>>>(mix, out);
}

// round 16
// speedup vs baseline: 1.1743x; 1.1743x over previous
#include <cuda_runtime.h>
#include <math.h>
#include <stdint.h>

#define NR 400000
#define DD 128
#define GG 256

// ---------------- scratch (device globals: no allocations allowed) ----------
__device__ float d_x1[(size_t)NR * DD];   // x1 = sub@W1+b1 (raw, pre-BN)
__device__ float d_hf[(size_t)NR * DD];   // h_fused
__device__ float d_hi[(size_t)NR * DD];   // h * ginv[batch]
__device__ float d_y [(size_t)NR * DD];   // pre-BN2 score-mlp hidden
__device__ float d_logit[NR];
__device__ float d_e[NR];

__device__ float d_cs1[DD], d_cq1[DD], d_cs2[DD], d_cq2[DD];  // BN column stats
__device__ float d_a1[DD], d_c1[DD], d_a2[DD], d_c2[DD];      // BN affine params
__device__ float d_gsum[GG * DD], d_gsq[GG * DD];
__device__ float d_gmean[GG * DD], d_ginv[GG * DD];
__device__ float d_gbias[GG * DD];
__device__ float d_cnt[GG];
__device__ unsigned d_smax[GG];
__device__ float d_denom[GG];
__device__ float d_accb[GG * DD];

// ordered-uint encoding for float atomicMax
__device__ __forceinline__ unsigned f2o(float f) {
    unsigned u = __float_as_uint(f);
    return (u & 0x80000000u) ? ~u : (u | 0x80000000u);
}
__device__ __forceinline__ float o2f(unsigned u) {
    return (u & 0x80000000u) ? __uint_as_float(u & 0x7fffffffu)
                             : __uint_as_float(~u);
}

__device__ __forceinline__ void mma8(float* c, const uint32_t* a, const uint32_t* b) {
    asm volatile(
        "mma.sync.aligned.m16n8k8.row.col.f32.tf32.tf32.f32 "
        "{%0,%1,%2,%3}, {%4,%5,%6,%7}, {%8,%9}, {%0,%1,%2,%3};"
        : "+f"(c[0]), "+f"(c[1]), "+f"(c[2]), "+f"(c[3])
        : "r"(a[0]), "r"(a[1]), "r"(a[2]), "r"(a[3]), "r"(b[0]), "r"(b[1]));
}

// ---------------- init ------------------------------------------------------
__global__ void init_k() {
    int i = blockIdx.x * 128 + threadIdx.x;   // grid covers GG*DD = 32768
    d_gsum[i] = 0.f; d_gsq[i] = 0.f; d_accb[i] = 0.f;
    if (i < DD) { d_cs1[i] = 0.f; d_cq1[i] = 0.f; d_cs2[i] = 0.f; d_cq2[i] = 0.f; }
    if (i < GG) { d_cnt[i] = 0.f; d_denom[i] = 0.f; d_smax[i] = 0u; }
}

// ---------------- pure cp.async tf32 mma.sync GEMM --------------------------
// CTA tile BM=128 x BN=64, BK=32. 256 thr = 8 warps (4m x 2n), warp = 32x32
// (2x4 m16n8k8), acc = 32 floats. A row-major smem (stride 36), B k-major
// (stride 72), both cp.async, double-buffered, one sync per chunk.
// blockIdx: row0 = (bx>>1)*128, col0 = (bx&1)*64.
// MODE 1: A = sub (K=64).          epi: x1 + BN1 stats (+ seg-stats(h) on half 0).
// MODE 2: A = [h | BN1relu(x1) inline] (K=256). epi: gate -> h_fused, write hi.
// MODE 3: A = [hf | hi] (K=256).   epi: y = acc + bs1 - gbias[g], BN2 stats.
#define AST 36                        // A smem row stride (floats)
#define ASTG (128 * AST)              // 4608 floats
#define BSTP 72                       // B smem k-row stride (floats)
#define BSTG (32 * BSTP)              // 2304 floats
#define SMEMSZ ((2 * ASTG + 2 * BSTG) * 4 + 2560)

template<int NCHUNK, int MODE>
__global__ __launch_bounds__(256, 3) void mma_gemm(
    const float* __restrict__ A0,    // sub / h / hf
    const float* __restrict__ A1,    // -   / x1 / hi
    const float* __restrict__ W,     // [K,128] row-major
    const float* __restrict__ bias,
    const int*   __restrict__ batch,
    const float* __restrict__ hs)    // h (MODE 1 seg-stats)
{
    extern __shared__ __align__(16) float dyn[];
    float* sbias = dyn + 2 * ASTG + 2 * BSTG;
    float* sa1   = sbias + 128;
    float* sc1   = sa1 + 128;
    int*   sbt   = (int*)(sc1 + 128);

    const int t = threadIdx.x;
    const int lane = t & 31;
    const int wid  = t >> 5;
    const int warp_m = wid & 3;          // 4 row tiles of 32
    const int warp_n = wid >> 2;         // 2 col tiles of 32
    const int lr = lane >> 2, lc = lane & 3;
    const int row0 = (blockIdx.x >> 1) * 128;
    const int col0 = (blockIdx.x & 1) * 64;

    if (t < DD) {
        sbias[t] = bias[t];
        if (MODE == 2) { sa1[t] = d_a1[t]; sc1[t] = d_c1[t]; }
    }

    float acc[2][4][4];
    #pragma unroll
    for (int i = 0; i < 2; i++)
        #pragma unroll
        for (int j = 0; j < 4; j++)
            #pragma unroll
            for (int e = 0; e < 4; e++) acc[i][j][e] = 0.f;

    auto issue = [&](int c, int s) {
        // ---- A: 128 rows x 32 floats -> row-major stride 36 ----
        const float* src;
        int strd;
        if (MODE == 1) { src = A0 + c * 32; strd = 64; }
        else { src = (c < 4) ? (A0 + c * 32) : (A1 + (c - 4) * 32); strd = DD; }
        uint32_t abase = (uint32_t)__cvta_generic_to_shared(dyn + s * ASTG);
        #pragma unroll
        for (int i = 0; i < 4; i++) {
            int p = t + i * 256;
            int row = p >> 3, seg = p & 7;
            uint32_t sa = abase + (uint32_t)(row * (AST * 4) + seg * 16);
            const float* ga = src + (size_t)(row0 + row) * strd + seg * 4;
            asm volatile("cp.async.cg.shared.global [%0], [%1], 16;"
                         :: "r"(sa), "l"(ga));
        }
        // ---- B: 32 k-rows x 64 cols -> k-major stride 72 ----
        uint32_t bbase = (uint32_t)__cvta_generic_to_shared(dyn + 2 * ASTG + s * BSTG);
        #pragma unroll
        for (int i = 0; i < 2; i++) {
            int p = t + i * 256;
            int krow = p >> 4, pc = p & 15;
            uint32_t sa = bbase + (uint32_t)(krow * (BSTP * 4) + pc * 16);
            const float* ga = W + (size_t)(c * 32 + krow) * DD + col0 + pc * 4;
            asm volatile("cp.async.cg.shared.global [%0], [%1], 16;"
                         :: "r"(sa), "l"(ga));
        }
        asm volatile("cp.async.commit_group;" ::: "memory");
    };

    issue(0, 0);
    for (int c = 0; c < NCHUNK; c++) {
        const int s = c & 1;
        asm volatile("cp.async.wait_group 0;" ::: "memory");
        __syncthreads();
        if (c + 1 < NCHUNK) issue(c + 1, 1 - s);

        const float* As = dyn + s * ASTG;
        const float* Bs = dyn + 2 * ASTG + s * BSTG;
        #pragma unroll
        for (int ks = 0; ks < 4; ks++) {
            const int k0 = ks * 8;
            // BN1+relu constants for MODE 2 chunks >= 4 (A half = raw x1)
            float aa = 1.f, ca = 0.f, ab = 1.f, cb = 0.f;
            if (MODE == 2 && c >= 4) {
                int kk = (c - 4) * 32 + k0 + lc;
                aa = sa1[kk];     ca = sc1[kk];
                ab = sa1[kk + 4]; cb = sc1[kk + 4];
            }
            uint32_t af[2][4];
            #pragma unroll
            for (int i = 0; i < 2; i++) {
                const float* ar = As + (warp_m * 32 + i * 16 + lr) * AST + k0 + lc;
                float a0 = ar[0], a1v = ar[8 * AST];
                float a2 = ar[4], a3v = ar[8 * AST + 4];
                if (MODE == 2 && c >= 4) {
                    a0  = fmaxf(aa * a0  + ca, 0.f);
                    a1v = fmaxf(aa * a1v + ca, 0.f);
                    a2  = fmaxf(ab * a2  + cb, 0.f);
                    a3v = fmaxf(ab * a3v + cb, 0.f);
                }
                af[i][0] = __float_as_uint(a0);
                af[i][1] = __float_as_uint(a1v);
                af[i][2] = __float_as_uint(a2);
                af[i][3] = __float_as_uint(a3v);
            }
            const float* b0 = Bs + (k0 + lc) * BSTP + warp_n * 32 + lr;
            const float* b4 = b0 + 4 * BSTP;
            #pragma unroll
            for (int j = 0; j < 4; j++) {
                uint32_t bf[2] = { __float_as_uint(b0[j * 8]),
                                   __float_as_uint(b4[j * 8]) };
                mma8(acc[0][j], af[0], bf);
                mma8(acc[1][j], af[1], bf);
            }
        }
    }

    // ---- epilogue ----
    // rows: row0 + warp_m*32 + i*16 + lr + hh*8 ; cols: col0 + warp_n*32 + j*8 + lc*2
    if (MODE == 1 || MODE == 3) {
        float* outp = (MODE == 1) ? d_x1 : d_y;
        float* gcs = (MODE == 1) ? d_cs1 : d_cs2;
        float* gcq = (MODE == 1) ? d_cq1 : d_cq2;
        float cs[4][2], cq[4][2];
        #pragma unroll
        for (int j = 0; j < 4; j++)
            #pragma unroll
            for (int e = 0; e < 2; e++) { cs[j][e] = 0.f; cq[j][e] = 0.f; }
        #pragma unroll
        for (int i = 0; i < 2; i++) {
            #pragma unroll
            for (int hh = 0; hh < 2; hh++) {
                int row = row0 + warp_m * 32 + i * 16 + lr + hh * 8;
                float* op = outp + (size_t)row * DD;
                int g = 0;
                if (MODE == 3) g = batch[row];
                #pragma unroll
                for (int j = 0; j < 4; j++) {
                    int col = col0 + warp_n * 32 + j * 8 + lc * 2;
                    float b0v = sbias[col], b1v = sbias[col + 1];
                    if (MODE == 3) {
                        float2 gb = *(const float2*)&d_gbias[g * DD + col];
                        b0v -= gb.x; b1v -= gb.y;
                    }
                    float v0 = acc[i][j][hh * 2 + 0] + b0v;
                    float v1 = acc[i][j][hh * 2 + 1] + b1v;
                    *(float2*)(op + col) = make_float2(v0, v1);
                    cs[j][0] += v0; cq[j][0] += v0 * v0;
                    cs[j][1] += v1; cq[j][1] += v1 * v1;
                }
            }
        }
        #pragma unroll
        for (int o = 4; o < 32; o <<= 1) {
            #pragma unroll
            for (int j = 0; j < 4; j++)
                #pragma unroll
                for (int e = 0; e < 2; e++) {
                    cs[j][e] += __shfl_xor_sync(0xffffffffu, cs[j][e], o);
                    cq[j][e] += __shfl_xor_sync(0xffffffffu, cq[j][e], o);
                }
        }
        if (lr == 0) {
            #pragma unroll
            for (int j = 0; j < 4; j++) {
                int col = col0 + warp_n * 32 + j * 8 + lc * 2;
                atomicAdd(&gcs[col],     cs[j][0]);
                atomicAdd(&gcs[col + 1], cs[j][1]);
                atomicAdd(&gcq[col],     cq[j][0]);
                atomicAdd(&gcq[col + 1], cq[j][1]);
            }
        }
    } else {  // MODE 2: gate sigmoid -> h_fused, and hi = h * ginv[batch]
        #pragma unroll
        for (int i = 0; i < 2; i++) {
            #pragma unroll
            for (int hh = 0; hh < 2; hh++) {
                int row = row0 + warp_m * 32 + i * 16 + lr + hh * 8;
                int g = batch[row];
                const float* hp = A0 + (size_t)row * DD;
                const float* xp = A1 + (size_t)row * DD;   // raw x1
                float* op  = d_hf + (size_t)row * DD;
                float* oip = d_hi + (size_t)row * DD;
                #pragma unroll
                for (int j = 0; j < 4; j++) {
                    int col = col0 + warp_n * 32 + j * 8 + lc * 2;
                    float2 h2 = *(const float2*)(hp + col);
                    float2 x2 = *(const float2*)(xp + col);
                    float2 gv = *(const float2*)&d_ginv[g * DD + col];
                    float se0 = fmaxf(sa1[col]   * x2.x + sc1[col],   0.f);
                    float se1 = fmaxf(sa1[col+1] * x2.y + sc1[col+1], 0.f);
                    float a0v = acc[i][j][hh * 2 + 0] + sbias[col];
                    float a1v = acc[i][j][hh * 2 + 1] + sbias[col + 1];
                    float g0 = 1.f / (1.f + expf(-a0v));
                    float g1 = 1.f / (1.f + expf(-a1v));
                    *(float2*)(op + col) =
                        make_float2(h2.x + g0 * se0, h2.y + g1 * se1);
                    *(float2*)(oip + col) =
                        make_float2(h2.x * gv.x, h2.y * gv.y);
                }
            }
        }
    }

    // ---- fused per-graph sum/sumsq of h (MODE 1, col-half 0 only) ----
    if (MODE == 1 && col0 == 0) {
        if (t < 128) sbt[t] = batch[row0 + t];
        __syncthreads();
        const int d = t & 127, half = t >> 7;
        const int base = half * 64;
        float s = 0.f, q = 0.f, cn = 0.f;
        int cur = sbt[base];
        for (int i = 0; i < 64; i++) {
            int g = sbt[base + i];
            if (g != cur) {
                atomicAdd(&d_gsum[cur * DD + d], s);
                atomicAdd(&d_gsq [cur * DD + d], q);
                if (d == 0) atomicAdd(&d_cnt[cur], cn);
                s = 0.f; q = 0.f; cn = 0.f; cur = g;
            }
            float v = hs[(size_t)(row0 + base + i) * DD + d];
            s += v; q += v * v; cn += 1.f;
        }
        atomicAdd(&d_gsum[cur * DD + d], s);
        atomicAdd(&d_gsq [cur * DD + d], q);
        if (d == 0) atomicAdd(&d_cnt[cur], cn);
    }
}

// ---------------- finalize BN1 + graph mean/inv-std -------------------------
__global__ void finalize1(const float* __restrict__ g1, const float* __restrict__ be1)
{
    int g = blockIdx.x, d = threadIdx.x;
    float cnt = fmaxf(d_cnt[g], 1.f);
    float m  = d_gsum[g * DD + d] / cnt;
    float sq = d_gsq [g * DD + d] / cnt;
    float sd = sqrtf(fmaxf(sq - m * m, 1e-8f));
    d_gmean[g * DD + d] = m;
    d_ginv [g * DD + d] = 1.f / (sd + 1e-8f);
    if (g == 0) {
        float mean = d_cs1[d] / (float)NR;
        float var  = d_cq1[d] / (float)NR - mean * mean;
        float a = g1[d] * rsqrtf(var + 1e-5f);
        d_a1[d] = a;
        d_c1[d] = be1[d] - mean * a;
    }
}

// ---------------- gbias[g,n] = sum_k gmean*ginv*Ws1[128+k, n] ----------------
__global__ void gbias_k(const float* __restrict__ Ws1) {
    __shared__ float sm[DD];
    int g = blockIdx.x, n = threadIdx.x;
    sm[n] = d_gmean[g * DD + n] * d_ginv[g * DD + n];
    __syncthreads();
    float a = 0.f;
    #pragma unroll 4
    for (int k = 0; k < DD; k++)
        a = fmaf(sm[k], Ws1[(size_t)(DD + k) * DD + n], a);
    d_gbias[g * DD + n] = a;
}

__global__ void finalize2(const float* __restrict__ g2, const float* __restrict__ be2)
{
    int d = threadIdx.x;
    float mean = d_cs2[d] / (float)NR;
    float var  = d_cq2[d] / (float)NR - mean * mean;
    float a = g2[d] * rsqrtf(var + 1e-5f);
    d_a2[d] = a;
    d_c2[d] = be2[d] - mean * a;
}

// ---------------- score logit: warp per row ---------------------------------
__global__ void logit_k(const float* __restrict__ Ws2, const float* __restrict__ bs2,
                        const int* __restrict__ batch)
{
    int w = threadIdx.x >> 5, l = threadIdx.x & 31;
    int row = blockIdx.x * 8 + w;
    float p = 0.f;
    #pragma unroll
    for (int c = 0; c < 4; c++) {
        int col = c * 32 + l;
        float z = fmaxf(d_a2[col] * d_y[(size_t)row * DD + col] + d_c2[col], 0.f);
        p = fmaf(z, Ws2[col], p);
    }
    #pragma unroll
    for (int o = 16; o; o >>= 1) p += __shfl_down_sync(0xffffffffu, p, o);
    if (l == 0) {
        float lg = p + bs2[0];
        d_logit[row] = lg;
        atomicMax(&d_smax[batch[row]], f2o(lg));
    }
}

// ---------------- exp + segment denom ---------------------------------------
__global__ void exp_k(const int* __restrict__ batch)
{
    int r = blockIdx.x * 256 + threadIdx.x;
    if (r >= NR) return;
    int g = batch[r];
    float mx = o2f(d_smax[g]);
    float e = expf(d_logit[r] - mx);
    d_e[r] = e;
    atomicAdd(&d_denom[g], e);
}

// ---------------- weighted segment sum of h_fused * score -------------------
__global__ void wsum_k(const int* __restrict__ batch)
{
    __shared__ int   sb[256];
    __shared__ float ss[256];
    int d = threadIdx.x;
    int r0 = blockIdx.x * 256;
    for (int i = d; i < 256; i += 128) {
        int r = r0 + i;
        if (r < NR) {
            int g = batch[r];
            sb[i] = g;
            ss[i] = d_e[r] / d_denom[g];
        } else sb[i] = -1;
    }
    __syncthreads();
    float a = 0.f;
    int cur = sb[0];
    for (int i = 0; i < 256; i++) {
        int g = sb[i];
        if (g < 0) break;
        if (g != cur) {
            atomicAdd(&d_accb[cur * DD + d], a);
            a = 0.f; cur = g;
        }
        a = fmaf(d_hf[(size_t)(r0 + i) * DD + d], ss[i], a);
    }
    atomicAdd(&d_accb[cur * DD + d], a);
}

// ---------------- final mix --------------------------------------------------
__global__ void final_k(const float* __restrict__ mix, float* __restrict__ out)
{
    int g = blockIdx.x, d = threadIdx.x;
    float alpha = 1.f / (1.f + expf(-mix[0]));
    out[g * DD + d] = alpha * d_accb[g * DD + d] + (1.f - alpha) * d_gmean[g * DD + d];
}

// ---------------- launch ------------------------------------------------------
extern "C" void kernel_launch(void* const* d_in, const int* in_sizes, int n_in,
                              void* d_out, int out_size)
{
    const float* h     = (const float*)d_in[0];
    const float* sub   = (const float*)d_in[1];
    const int*   batch = (const int*)  d_in[2];
    const float* W1    = (const float*)d_in[3];
    const float* b1    = (const float*)d_in[4];
    const float* g1    = (const float*)d_in[5];
    const float* be1   = (const float*)d_in[6];
    const float* Wg    = (const float*)d_in[7];
    const float* bg    = (const float*)d_in[8];
    const float* Ws1   = (const float*)d_in[9];
    const float* bs1   = (const float*)d_in[10];
    const float* g2    = (const float*)d_in[11];
    const float* be2   = (const float*)d_in[12];
    const float* Ws2   = (const float*)d_in[13];
    const float* bs2   = (const float*)d_in[14];
    const float* mix   = (const float*)d_in[15];
    float* out = (float*)d_out;

    float* x1p; cudaGetSymbolAddress((void**)&x1p, d_x1);
    float* hfp; cudaGetSymbolAddress((void**)&hfp, d_hf);
    float* hip; cudaGetSymbolAddress((void**)&hip, d_hi);

    static int attr_done = 0;
    if (!attr_done) {
        cudaFuncSetAttribute(mma_gemm<2, 1>,
            cudaFuncAttributeMaxDynamicSharedMemorySize, SMEMSZ);
        cudaFuncSetAttribute(mma_gemm<8, 2>,
            cudaFuncAttributeMaxDynamicSharedMemorySize, SMEMSZ);
        cudaFuncSetAttribute(mma_gemm<8, 3>,
            cudaFuncAttributeMaxDynamicSharedMemorySize, SMEMSZ);
        attr_done = 1;
    }

    const int NB = (NR / 128) * 2;   // 6250 blocks (row tile x 2 col halves)

    init_k<<<GG * DD / 128, 128>>>();
    mma_gemm<2, 1><<<NB, 256, SMEMSZ>>>(sub, sub, W1, b1, batch, h);
    finalize1<<<GG, 128>>>(g1, be1);
    gbias_k<<<GG, DD>>>(Ws1);
    mma_gemm<8, 2><<<NB, 256, SMEMSZ>>>(h, x1p, Wg, bg, batch, h);
    mma_gemm<8, 3><<<NB, 256, SMEMSZ>>>(hfp, hip, Ws1, bs1, batch, h);
    finalize2<<<1, 128>>>(g2, be2);
    logit_k<<<NR / 8, 256>>>(Ws2, bs2, batch);
    exp_k<<<(NR + 255) / 256, 256>>>(batch);
    wsum_k<<<(NR + 255) / 256, 128>>>(batch);
    final_k<<<GG, 128>>>(mix, out);
}